// round 16
// baseline (speedup 1.0000x reference)
#include <cuda_runtime.h>
#include <cuda_fp16.h>
#include <cstdint>

// ---------------------------------------------------------------------------
// Decoder_84731114815924  (B=4, N=256, D=32, H=512)
// R16: barrier-free main loop — all GEMM operands read via __ldg (L1-cached)
// from pre-packed fragment-major gmem; no cp.async, no smem tiles, no
// per-chunk __syncthreads. Warps fully independent. HMMA count unchanged.
// ---------------------------------------------------------------------------

#define BNN   262144

__device__ __align__(16) uint32_t g_tmph[1024 * 16 * 512]; // 32 MB GEMM1 B-frags
__device__ __align__(16) uint32_t g_w2h[16 * 4096];        // 256 KB GEMM2 B-frags
__device__ __align__(16) uint32_t g_zh[16384];             // 64 KB GEMM1 A-frags

__device__ __forceinline__ uint32_t ph2(float a, float b) {
    __half2 h = __floats2half2_rn(a, b);
    return *(uint32_t*)&h;
}

#define MMA_F16(D, A, B0, B1)                                               \
    asm volatile(                                                           \
        "mma.sync.aligned.m16n8k16.row.col.f32.f16.f16.f32 "                \
        "{%0,%1,%2,%3}, {%4,%5,%6,%7}, {%8,%9}, {%0,%1,%2,%3};\n"           \
        : "+f"(D[0]), "+f"(D[1]), "+f"(D[2]), "+f"(D[3])                    \
        : "r"(A[0]), "r"(A[1]), "r"(A[2]), "r"(A[3]), "r"(B0), "r"(B1))

// ---------------------------------------------------------------------------
// Merged preprocessing kernel, 1344 blocks x 256 threads (layouts = R12/R15):
//   [0,1024): stage-A  tmp GEMM -> fp16 GEMM1 B-frags
//   [1024,1280): pack W2 -> fp16 GEMM2 B-frags (uint4-tile layout)
//   [1280,1344): pack z -> fp16 GEMM1 A-frags
// ---------------------------------------------------------------------------
__global__ __launch_bounds__(256) void preprocess_kernel(
    const float* __restrict__ z, const float* __restrict__ W1,
    const float* __restrict__ W2)
{
    __shared__ float zt[32][68];
    __shared__ float wt[32][264];
    const int bx  = blockIdx.x;
    const int tid = threadIdx.x;

    if (bx < 1024) {
        const int sub = bx & 63;
        const int oct = sub & 3;
        const int hg  = sub >> 2;
        const int bi0 = (bx >> 6) * 64;
        const int c0  = oct * 8, h0 = hg * 32;

        for (int idx = tid; idx < 64 * 32; idx += 256) {
            int r = idx >> 5, a = idx & 31;
            zt[a][r] = z[(bi0 + r) * 32 + a];
        }
        for (int idx = tid; idx < 32 * 256; idx += 256) {
            int a = idx >> 8, col = idx & 255;
            int ci = col >> 5, hi = col & 31;
            wt[a][col] = W1[a * 16384 + (c0 + ci) * 512 + h0 + hi];
        }
        __syncthreads();

        const int tm = tid >> 4;
        const int tn = tid & 15;

        float acc[2][4][8];
#pragma unroll
        for (int u = 0; u < 2; u++)
#pragma unroll
            for (int i = 0; i < 4; i++)
#pragma unroll
                for (int j = 0; j < 8; j++) acc[u][i][j] = 0.f;

#pragma unroll
        for (int k = 0; k < 32; k++) {
            float4 a4 = *(const float4*)&zt[k][tm * 4];
            float av[4] = { a4.x, a4.y, a4.z, a4.w };
            float b0[8], b1[8];
#pragma unroll
            for (int j = 0; j < 8; j++) {
                b0[j] = wt[k][j * 32 + tn];
                b1[j] = wt[k][j * 32 + tn + 16];
            }
#pragma unroll
            for (int i = 0; i < 4; i++)
#pragma unroll
                for (int j = 0; j < 8; j++) {
                    acc[0][i][j] = fmaf(av[i], b0[j], acc[0][i][j]);
                    acc[1][i][j] = fmaf(av[i], b1[j], acc[1][i][j]);
                }
        }

        const int s = oct >> 1, bh = oct & 1;
#pragma unroll
        for (int u = 0; u < 2; u++) {
            const int h   = h0 + tn + u * 16;
            const int chk = h >> 5;
            const int nt  = (h >> 3) & 3;
            const int g   = h & 7;
#pragma unroll
            for (int i = 0; i < 4; i++) {
                const int bi = bi0 + tm * 4 + i;
                uint4 v;
                v.x = ph2(acc[u][i][0], acc[u][i][1]);
                v.y = ph2(acc[u][i][2], acc[u][i][3]);
                v.z = ph2(acc[u][i][4], acc[u][i][5]);
                v.w = ph2(acc[u][i][6], acc[u][i][7]);
                ((uint4*)g_tmph)[(size_t)(bi * 16 + chk) * 128
                                 + ((nt * 2 + s) * 2 + bh) * 8 + g] = v;
            }
        }
    } else if (bx < 1280) {
        const int gid  = (bx - 1024) * 256 + tid;   // 65536
        const int bh   = gid & 1;
        const int s    = (gid >> 1) & 1;
        const int lane = (gid >> 2) & 31;
        const int nt   = (gid >> 7) & 31;
        const int chk  = gid >> 12;
        const int h  = chk * 32 + s * 16 + bh * 8 + (lane & 3) * 2;
        const int k2 = nt * 8 + (lane >> 2);
        g_w2h[gid] = ph2(W2[h * 256 + k2], W2[(h + 1) * 256 + k2]);
    } else {
        const int gid  = (bx - 1280) * 256 + tid;   // 16384
        const int r    = gid & 3;
        const int lane = (gid >> 2) & 31;
        const int s    = (gid >> 7) & 1;
        const int tile = gid >> 8;
        const int g = lane >> 2, t = lane & 3;
        const int row = tile * 16 + g + (r & 1) * 8;
        const int col = s * 16 + t * 2 + (r >> 1) * 8;
        g_zh[gid] = ph2(z[row * 32 + col], z[row * 32 + col + 1]);
    }
}

// ---------------------------------------------------------------------------
// Main fused kernel: grid 4096 = (b, i, jt of 4), 128 thr, 3 CTAs/SM.
// Warp w owns j rows [w*16, +16) end-to-end; operands via __ldg (L1):
//   GEMM1: 16 LDG.32 (tmp frags) -> 8 MMAs -> relu+bias -> fp16 A-frags (regs)
//   GEMM2: 32 LDG.128 (W2 frags) -> 64 MMAs, acc2[32][4] fp32.
// ONE __syncthreads total (bias staging); mainloop barrier-free.
// ---------------------------------------------------------------------------
__global__ __launch_bounds__(128, 3) void decoder_main_kernel(
    const float* __restrict__ motif,
    const float* __restrict__ b1, const float* __restrict__ b2,
    const float* __restrict__ W3, const float* __restrict__ b3,
    float* __restrict__ out)
{
    __shared__ float s_bias[1024];           // b1[512] b2[256] w3[256]
    float* s_b1 = s_bias;
    float* s_b2 = s_bias + 512;
    float* s_w3 = s_bias + 768;

    const int cta = blockIdx.x;
    const int jt  = cta & 3;
    const int i   = (cta >> 2) & 255;
    const int b   = cta >> 10;
    const int bi  = b * 256 + i;
    const int j0  = jt * 64;

    const int tid  = threadIdx.x;
    const int w    = tid >> 5;
    const int lane = tid & 31;
    const int g    = lane >> 2;
    const int t    = lane & 3;

    for (int idx = tid; idx < 1024; idx += 128) {
        if (idx < 512)       s_bias[idx] = b1[idx];
        else if (idx < 768)  s_bias[idx] = b2[idx - 512];
        else                 s_bias[idx] = W3[idx - 768];
    }

    // ---- z A-frags, register-resident (chunk-invariant) ------------------
    uint32_t za[2][4];
    {
        const int tile = ((b * 256 + j0) >> 4) + w;
        const uint4* zf = (const uint4*)g_zh;
#pragma unroll
        for (int s = 0; s < 2; s++) {
            uint4 v = __ldg(&zf[(tile * 2 + s) * 32 + lane]);
            za[s][0] = v.x; za[s][1] = v.y; za[s][2] = v.z; za[s][3] = v.w;
        }
    }
    __syncthreads();                         // the only barrier

    float acc2[32][4];
#pragma unroll
    for (int nt = 0; nt < 32; nt++)
#pragma unroll
        for (int r = 0; r < 4; r++) acc2[nt][r] = 0.f;

    const uint32_t* tbase = g_tmph + (size_t)bi * 16 * 512;

    for (int chk = 0; chk < 16; chk++) {
        const uint32_t* tb = tbase + chk * 512;
        const uint4*    wb = (const uint4*)(g_w2h + chk * 4096) + lane;

        // ---- GEMM1: acc1 = z_rows(w) . tmp^T  (16j x 32h) ----------------
        float acc1[4][4];
#pragma unroll
        for (int nt = 0; nt < 4; nt++)
#pragma unroll
            for (int r = 0; r < 4; r++) acc1[nt][r] = 0.f;

#pragma unroll
        for (int s = 0; s < 2; s++)
#pragma unroll
            for (int nt = 0; nt < 4; nt++) {
                uint32_t b0 = __ldg(&tb[((nt * 2 + s) * 2 + 0) * 32 + lane]);
                uint32_t bb = __ldg(&tb[((nt * 2 + s) * 2 + 1) * 32 + lane]);
                MMA_F16(acc1[nt], za[s], b0, bb);
            }

        // bias + relu + fp16 pack: C-frag -> A-frag, all in registers
        uint32_t h1h[4][2];
#pragma unroll
        for (int nt = 0; nt < 4; nt++) {
            const float* bb = s_b1 + chk * 32 + nt * 8 + t * 2;
            float v0 = fmaxf(acc1[nt][0] + bb[0], 0.f);
            float v1 = fmaxf(acc1[nt][1] + bb[1], 0.f);
            float v2 = fmaxf(acc1[nt][2] + bb[0], 0.f);
            float v3 = fmaxf(acc1[nt][3] + bb[1], 0.f);
            h1h[nt][0] = ph2(v0, v1);
            h1h[nt][1] = ph2(v2, v3);
        }

        // ---- GEMM2: acc2 += h1(16j) . W2chunk, nt-pair interleaved -------
        {
            uint32_t A0[4] = { h1h[0][0], h1h[0][1], h1h[1][0], h1h[1][1] };
            uint32_t A1[4] = { h1h[2][0], h1h[2][1], h1h[3][0], h1h[3][1] };
#pragma unroll
            for (int np = 0; np < 16; np++) {
                uint4 bv0 = __ldg(wb + (2 * np) * 32);
                uint4 bv1 = __ldg(wb + (2 * np + 1) * 32);
                MMA_F16(acc2[2 * np],     A0, bv0.x, bv0.y);
                MMA_F16(acc2[2 * np + 1], A0, bv1.x, bv1.y);
                MMA_F16(acc2[2 * np],     A1, bv0.z, bv0.w);
                MMA_F16(acc2[2 * np + 1], A1, bv1.z, bv1.w);
            }
        }
    }

    // ---- epilogue: relu(+b2) . W3 (full k2 in-warp), quad-reduce ---------
    float ps0 = 0.f, ps1 = 0.f;
#pragma unroll
    for (int nt = 0; nt < 32; nt++) {
        const int k = nt * 8 + t * 2;
        float h2a = fmaxf(acc2[nt][0] + s_b2[k],     0.f);
        float h2b = fmaxf(acc2[nt][1] + s_b2[k + 1], 0.f);
        float h2c = fmaxf(acc2[nt][2] + s_b2[k],     0.f);
        float h2d = fmaxf(acc2[nt][3] + s_b2[k + 1], 0.f);
        ps0 = fmaf(h2a, s_w3[k], ps0);  ps0 = fmaf(h2b, s_w3[k + 1], ps0);
        ps1 = fmaf(h2c, s_w3[k], ps1);  ps1 = fmaf(h2d, s_w3[k + 1], ps1);
    }
    ps0 += __shfl_xor_sync(0xffffffffu, ps0, 1);
    ps0 += __shfl_xor_sync(0xffffffffu, ps0, 2);
    ps1 += __shfl_xor_sync(0xffffffffu, ps1, 1);
    ps1 += __shfl_xor_sync(0xffffffffu, ps1, 2);

    if (t == 0) {
        const float b3v = b3[0];
        const float mi  = motif[b * 256 + i];
#pragma unroll
        for (int u = 0; u < 2; u++) {
            const int j = j0 + w * 16 + g + u * 8;
            float logit = ((u ? ps1 : ps0) + b3v) * (mi * motif[b * 256 + j]);
            float cmap  = 1.f / (1.f + __expf(-logit));
            size_t base = (size_t)bi * 256 + j;
            out[base]       = cmap;
            out[BNN + base] = logit;
        }
    }
}

// ---------------------------------------------------------------------------
extern "C" void kernel_launch(void* const* d_in, const int* in_sizes, int n_in,
                              void* d_out, int out_size)
{
    const float* z     = (const float*)d_in[0];
    const float* motif = (const float*)d_in[1];
    const float* W1    = (const float*)d_in[3];
    const float* b1    = (const float*)d_in[4];
    const float* W2    = (const float*)d_in[5];
    const float* b2    = (const float*)d_in[6];
    const float* W3    = (const float*)d_in[7];
    const float* b3    = (const float*)d_in[8];
    float* out = (float*)d_out;

    (void)in_sizes; (void)n_in; (void)out_size;

    preprocess_kernel<<<1344, 256>>>(z, W1, W2);
    decoder_main_kernel<<<4096, 128>>>(motif, b1, b2, W3, b3, out);
}